// round 13
// baseline (speedup 1.0000x reference)
#include <cuda_runtime.h>
#include <cuda_fp16.h>
#include <cstdint>

// ---------------------------------------------------------------------------
// 2-layer GCN:  out = Â( relu( Â(xW1)+b1 ) W2 ) + b2,  Â = D^-1/2 (A+I) D^-1/2
// edge_index is INT32.
// GEMMs: HMMA mma.sync.m16n8k16 (fp16 in, fp32 accum), H stored fp16.
// GEMM2 epilogue pre-scales rows by dis[row]; agg64 needs no per-edge dis.
// CSR build (2-kernel scan) overlapped with GEMM1; agg128->gemm2 chunk-pipelined.
// ---------------------------------------------------------------------------

static constexpr int NN = 100000;
static constexpr int NE = 1600000;
static constexpr int SCAN_B = (NN + 1023) / 1024;   // 98 blocks
static constexpr int CHUNK  = 25088;                // 196 * 128
static constexpr int NCHUNK = 4;

__device__ __half g_hh1[(size_t)NN * 128];  // x @ W1                  (fp16)
__device__ __half g_r1[(size_t)NN * 128];   // relu(Â h1 + b1)         (fp16)
__device__ __half g_hh2[(size_t)NN * 64];   // dis[row]*(relu(a1)@W2)  (fp16)
__device__ float  g_dis[NN];                // (1+indeg)^-1/2
__device__ int    g_indeg[NN];
__device__ int    g_incl[NN];
__device__ int    g_bsum[SCAN_B];
__device__ int    g_rowptr[NN + 1];
__device__ int    g_cursor[NN];
__device__ int    g_csrc[NE];               // CSR src ids (grouped by dst)

// ---------------------------------------------------------------------------
// helpers
// ---------------------------------------------------------------------------
__device__ __forceinline__ unsigned h2u(__half2 h) {
    return *reinterpret_cast<unsigned*>(&h);
}
__device__ __forceinline__ float2 u2f2(unsigned u) {
    return __half22float2(*reinterpret_cast<__half2*>(&u));
}
__device__ __forceinline__ void mma16816(float* c, const unsigned* a,
                                         const unsigned* b) {
    asm volatile(
        "mma.sync.aligned.m16n8k16.row.col.f32.f16.f16.f32 "
        "{%0,%1,%2,%3}, {%4,%5,%6,%7}, {%8,%9}, {%0,%1,%2,%3};"
        : "+f"(c[0]), "+f"(c[1]), "+f"(c[2]), "+f"(c[3])
        : "r"(a[0]), "r"(a[1]), "r"(a[2]), "r"(a[3]), "r"(b[0]), "r"(b[1]));
}

// ---------------------------------------------------------------------------
// degree count (int4-vectorized; NE % 4 == 0)
// ---------------------------------------------------------------------------
__global__ void k_zero_indeg() {
    int i = blockIdx.x * blockDim.x + threadIdx.x;
    if (i < NN) g_indeg[i] = 0;
}

__global__ void k_deg_count(const int* __restrict__ ei) {
    int i = blockIdx.x * blockDim.x + threadIdx.x;
    if (i < NE / 4) {
        int4 d = ((const int4*)(ei + NE))[i];
        atomicAdd(&g_indeg[d.x], 1);
        atomicAdd(&g_indeg[d.y], 1);
        atomicAdd(&g_indeg[d.z], 1);
        atomicAdd(&g_indeg[d.w], 1);
    }
}

// ---------------------------------------------------------------------------
// scan pass 1 (2-level warp shuffle) + dis fused
// ---------------------------------------------------------------------------
__global__ void __launch_bounds__(1024) k_scan_blk() {
    __shared__ int wsum[32];
    const int t = threadIdx.x, lane = t & 31, wid = t >> 5;
    const int idx = blockIdx.x * 1024 + t;
    int deg = (idx < NN) ? g_indeg[idx] : 0;
    if (idx < NN) g_dis[idx] = rsqrtf((float)(deg + 1));   // fused k_dis
    int s = deg;
#pragma unroll
    for (int o = 1; o < 32; o <<= 1) {
        int n = __shfl_up_sync(0xffffffffu, s, o);
        if (lane >= o) s += n;
    }
    if (lane == 31) wsum[wid] = s;
    __syncthreads();
    if (wid == 0) {
        int ws = wsum[lane];
#pragma unroll
        for (int o = 1; o < 32; o <<= 1) {
            int n = __shfl_up_sync(0xffffffffu, ws, o);
            if (lane >= o) ws += n;
        }
        wsum[lane] = ws;
    }
    __syncthreads();
    int incl = (wid ? wsum[wid - 1] : 0) + s;
    if (idx < NN) g_incl[idx] = incl;
    if (t == 1023) g_bsum[blockIdx.x] = incl;      // raw block total
}

// ---------------------------------------------------------------------------
// scan pass 2: each block reduces its own prefix over bsum (no middle kernel)
// ---------------------------------------------------------------------------
__global__ void __launch_bounds__(1024) k_scan_fin() {
    __shared__ int s_off, s_tot;
    const int t = threadIdx.x;
    if (t < 32) {
        int pre = 0, tot = 0;
        for (int i = t; i < SCAN_B; i += 32) {
            int v = g_bsum[i];
            tot += v;
            if (i < blockIdx.x) pre += v;
        }
#pragma unroll
        for (int o = 16; o; o >>= 1) {
            pre += __shfl_down_sync(0xffffffffu, pre, o);
            tot += __shfl_down_sync(0xffffffffu, tot, o);
        }
        if (t == 0) { s_off = pre; s_tot = tot; }
    }
    __syncthreads();
    const int off = s_off;
    int idx = blockIdx.x * 1024 + t;
    if (idx < NN) {
        int r = g_incl[idx] - g_indeg[idx] + off;  // exclusive
        g_rowptr[idx] = r;
        g_cursor[idx] = r;
    }
    if (blockIdx.x == SCAN_B - 1 && t == 0) g_rowptr[NN] = s_tot;
}

__global__ void k_csr_fill(const int* __restrict__ ei) {
    int i = blockIdx.x * blockDim.x + threadIdx.x;
    if (i < NE / 4) {
        int4 s = ((const int4*)ei)[i];
        int4 d = ((const int4*)(ei + NE))[i];
        g_csrc[atomicAdd(&g_cursor[d.x], 1)] = s.x;
        g_csrc[atomicAdd(&g_cursor[d.y], 1)] = s.y;
        g_csrc[atomicAdd(&g_cursor[d.z], 1)] = s.z;
        g_csrc[atomicAdd(&g_cursor[d.w], 1)] = s.w;
    }
}

// ---------------------------------------------------------------------------
// HMMA GEMM: H[row0+.., BN] = A @ W, fp16 in, fp32 accum, fp16 out.
// 256 thr = 8 warps (4m x 2n), BM=128 per block, KC=64 chunks. row0 = chunk base.
// SRC=0: A = x (fp32, converted), store h.
// SRC=1: A = g_r1 (fp16), store dis[row]*h   (pre-scaled for agg64).
// ---------------------------------------------------------------------------
template <int BN, int SRC>
__global__ void __launch_bounds__(256, 2)
k_gemm_mma(const float* __restrict__ Ap, const float* __restrict__ W,
           int row0, int M) {
    constexpr int K   = 128;
    constexpr int KC  = 64;
    constexpr int BM  = 128;
    constexpr int SA  = KC + 8;          // 72 halfs (conflict-free fragments)
    constexpr int SB  = KC + 8;
    constexpr int WN  = BN / 2;          // warp n-tile (64 or 32)
    constexpr int NT  = WN / 8;          // n8 tiles per warp (8 or 4)

    __shared__ __half As[BM * SA];       // [m][k]
    __shared__ __half Bs[BN * SB];       // [n][k]  (transposed for col-major B)

    const int tid  = threadIdx.x;
    const int wid  = tid >> 5;
    const int lane = tid & 31;
    const int gid  = lane >> 2;          // 0..7
    const int tig  = lane & 3;           // 0..3
    const int wm   = wid >> 1;           // 0..3
    const int wn   = wid & 1;            // 0..1
    const int rowbase = row0 + blockIdx.x * BM;

    float acc[2][NT][4];
#pragma unroll
    for (int mi = 0; mi < 2; mi++)
#pragma unroll
        for (int nj = 0; nj < NT; nj++)
#pragma unroll
            for (int q = 0; q < 4; q++) acc[mi][nj][q] = 0.f;

    for (int kk = 0; kk < K; kk += KC) {
        // --- A chunk (BM x 64) -> As[m][k] fp16 ---
        if (SRC == 0) {
            const float4* A4 = (const float4*)Ap;
#pragma unroll
            for (int t = 0; t < 8; t++) {
                int f  = tid + t * 256;
                int r  = f >> 4;             // 16 float4 per 64-col row
                int c4 = f & 15;
                int grow = rowbase + r;
                float4 v = make_float4(0.f, 0.f, 0.f, 0.f);
                if (grow < M) v = A4[(size_t)grow * 32 + (kk >> 2) + c4];
                uint2 pk;
                pk.x = h2u(__floats2half2_rn(v.x, v.y));
                pk.y = h2u(__floats2half2_rn(v.z, v.w));
                *(uint2*)&As[r * SA + c4 * 4] = pk;
            }
        } else {
            const uint2* A2 = (const uint2*)g_r1;   // 4 halfs per uint2, 32/row
#pragma unroll
            for (int t = 0; t < 8; t++) {
                int f  = tid + t * 256;
                int r  = f >> 4;
                int c4 = f & 15;
                int grow = rowbase + r;
                uint2 v = make_uint2(0u, 0u);
                if (grow < M) v = A2[(size_t)grow * 32 + (kk >> 2) + c4];
                *(uint2*)&As[r * SA + c4 * 4] = v;
            }
        }
        // --- W chunk (64 x BN) -> Bs[n][k] fp16 (transpose; coalesced reads) ---
        {
            constexpr int TPN  = 256 / BN;     // threads per n (2 or 4)
            constexpr int KPER = KC / TPN;     // k's per thread (32 or 16)
            int n  = tid % BN;
            int kb = (tid / BN) * KPER;
#pragma unroll
            for (int i = 0; i < KPER; i++) {
                float v = W[(size_t)(kk + kb + i) * BN + n];
                Bs[n * SB + kb + i] = __float2half_rn(v);
            }
        }
        __syncthreads();

#pragma unroll
        for (int ks = 0; ks < KC / 16; ks++) {
            unsigned a[2][4];
#pragma unroll
            for (int mi = 0; mi < 2; mi++) {
                const __half* base =
                    &As[(wm * 32 + mi * 16 + gid) * SA + ks * 16 + tig * 2];
                a[mi][0] = *(const unsigned*)base;
                a[mi][1] = *(const unsigned*)(base + 8 * SA);
                a[mi][2] = *(const unsigned*)(base + 8);
                a[mi][3] = *(const unsigned*)(base + 8 * SA + 8);
            }
#pragma unroll
            for (int nj = 0; nj < NT; nj++) {
                const __half* bb =
                    &Bs[(wn * WN + nj * 8 + gid) * SB + ks * 16 + tig * 2];
                unsigned b[2];
                b[0] = *(const unsigned*)bb;
                b[1] = *(const unsigned*)(bb + 8);
                mma16816(acc[0][nj], a[0], b);
                mma16816(acc[1][nj], a[1], b);
            }
        }
        __syncthreads();
    }

    // --- epilogue: fp16 store of H (SRC==1: pre-scaled by dis[row]) ---
    __half* H = (SRC == 0) ? g_hh1 : g_hh2;
#pragma unroll
    for (int mi = 0; mi < 2; mi++) {
#pragma unroll
        for (int rr = 0; rr < 2; rr++) {
            int grow = rowbase + wm * 32 + mi * 16 + gid + rr * 8;
            if (grow < M) {
                float sc = (SRC == 1) ? g_dis[grow] : 1.0f;
#pragma unroll
                for (int nj = 0; nj < NT; nj++) {
                    int n = wn * WN + nj * 8 + tig * 2;
                    float v0 = acc[mi][nj][rr * 2];
                    float v1 = acc[mi][nj][rr * 2 + 1];
                    if (SRC == 1) { v0 *= sc; v1 *= sc; }
                    *(unsigned*)&H[(size_t)grow * BN + n] =
                        h2u(__floats2half2_rn(v0, v1));
                }
            }
        }
    }
}

// ---------------------------------------------------------------------------
// aggregation, warp-per-node, fp32 accumulate. Nodes [n0, n1).
// C=128 (h=g_hh1, raw):  r1[w] = relu( dw*(dw*h[w] + Σ dis[s]*h[s]) + b )  fp16
// C=64  (h=g_hh2, pre-scaled): out[w] = dw*(hh2[w] + Σ hh2[s]) + b         fp32
// ---------------------------------------------------------------------------
template <int C>
__global__ void __launch_bounds__(256)
k_agg(const float* __restrict__ bias, float* __restrict__ outp, int n0, int n1) {
    const __half* h = (C == 128) ? g_hh1 : g_hh2;

    const int w = n0 + ((blockIdx.x * blockDim.x + threadIdx.x) >> 5);
    if (w >= n1) return;
    const int lane = threadIdx.x & 31;
    const int beg = g_rowptr[w];
    const int end = g_rowptr[w + 1];
    const float dw = g_dis[w];

    if constexpr (C == 128) {
        const uint2* h8 = (const uint2*)h;          // 4 halfs per uint2, 32/row
        uint2 raw = h8[(size_t)w * 32 + lane];
        float2 f0 = u2f2(raw.x), f1 = u2f2(raw.y);
        float4 acc = make_float4(f0.x * dw, f0.y * dw, f1.x * dw, f1.y * dw);
        int j = beg;
        for (; j + 3 < end; j += 4) {               // 4-way for MLP
            int   s0 = g_csrc[j],   s1 = g_csrc[j+1], s2 = g_csrc[j+2], s3 = g_csrc[j+3];
            float w0 = g_dis[s0],   w1 = g_dis[s1],   w2 = g_dis[s2],   w3 = g_dis[s3];
            uint2 r0 = __ldg(h8 + (size_t)s0 * 32 + lane);
            uint2 r1 = __ldg(h8 + (size_t)s1 * 32 + lane);
            uint2 r2 = __ldg(h8 + (size_t)s2 * 32 + lane);
            uint2 r3 = __ldg(h8 + (size_t)s3 * 32 + lane);
            float2 a0 = u2f2(r0.x), b0 = u2f2(r0.y);
            float2 a1 = u2f2(r1.x), b1 = u2f2(r1.y);
            float2 a2 = u2f2(r2.x), b2 = u2f2(r2.y);
            float2 a3 = u2f2(r3.x), b3 = u2f2(r3.y);
            acc.x = fmaf(a0.x, w0, acc.x); acc.y = fmaf(a0.y, w0, acc.y);
            acc.z = fmaf(b0.x, w0, acc.z); acc.w = fmaf(b0.y, w0, acc.w);
            acc.x = fmaf(a1.x, w1, acc.x); acc.y = fmaf(a1.y, w1, acc.y);
            acc.z = fmaf(b1.x, w1, acc.z); acc.w = fmaf(b1.y, w1, acc.w);
            acc.x = fmaf(a2.x, w2, acc.x); acc.y = fmaf(a2.y, w2, acc.y);
            acc.z = fmaf(b2.x, w2, acc.z); acc.w = fmaf(b2.y, w2, acc.w);
            acc.x = fmaf(a3.x, w3, acc.x); acc.y = fmaf(a3.y, w3, acc.y);
            acc.z = fmaf(b3.x, w3, acc.z); acc.w = fmaf(b3.y, w3, acc.w);
        }
        for (; j < end; j++) {
            int   s0 = g_csrc[j];
            float w0 = g_dis[s0];
            uint2 r0 = __ldg(h8 + (size_t)s0 * 32 + lane);
            float2 a0 = u2f2(r0.x), b0 = u2f2(r0.y);
            acc.x = fmaf(a0.x, w0, acc.x); acc.y = fmaf(a0.y, w0, acc.y);
            acc.z = fmaf(b0.x, w0, acc.z); acc.w = fmaf(b0.y, w0, acc.w);
        }
        const float4 bb = ((const float4*)bias)[lane];
        float rx = fmaxf(fmaf(acc.x, dw, bb.x), 0.f);
        float ry = fmaxf(fmaf(acc.y, dw, bb.y), 0.f);
        float rz = fmaxf(fmaf(acc.z, dw, bb.z), 0.f);
        float rw = fmaxf(fmaf(acc.w, dw, bb.w), 0.f);
        uint2 pk;
        pk.x = h2u(__floats2half2_rn(rx, ry));
        pk.y = h2u(__floats2half2_rn(rz, rw));
        ((uint2*)g_r1)[(size_t)w * 32 + lane] = pk;   // relu(a1) in fp16
    } else {
        const unsigned* h4 = (const unsigned*)h;    // 2 halfs per u32, 32/row
        float2 hv = u2f2(h4[(size_t)w * 32 + lane]);
        float2 acc = hv;                            // hh2[w] = dw*h2[w] already
        int j = beg;
        for (; j + 3 < end; j += 4) {
            int s0 = g_csrc[j], s1 = g_csrc[j+1], s2 = g_csrc[j+2], s3 = g_csrc[j+3];
            float2 v0 = u2f2(__ldg(h4 + (size_t)s0 * 32 + lane));
            float2 v1 = u2f2(__ldg(h4 + (size_t)s1 * 32 + lane));
            float2 v2 = u2f2(__ldg(h4 + (size_t)s2 * 32 + lane));
            float2 v3 = u2f2(__ldg(h4 + (size_t)s3 * 32 + lane));
            acc.x += v0.x + v1.x; acc.y += v0.y + v1.y;
            acc.x += v2.x + v3.x; acc.y += v2.y + v3.y;
        }
        for (; j < end; j++) {
            int s0 = g_csrc[j];
            float2 v0 = u2f2(__ldg(h4 + (size_t)s0 * 32 + lane));
            acc.x += v0.x; acc.y += v0.y;
        }
        const float2 bb = ((const float2*)bias)[lane];
        ((float2*)outp)[(size_t)w * 32 + lane] =
            make_float2(fmaf(acc.x, dw, bb.x), fmaf(acc.y, dw, bb.y));
    }
}

// ---------------------------------------------------------------------------
extern "C" void kernel_launch(void* const* d_in, const int* in_sizes, int n_in,
                              void* d_out, int out_size) {
    (void)in_sizes; (void)n_in; (void)out_size;
    const float* x  = (const float*)d_in[0];
    const int*   ei = (const int*)d_in[1];     // int32 (JAX x64 disabled)
    const float* W1 = (const float*)d_in[2];
    const float* b1 = (const float*)d_in[3];
    const float* W2 = (const float*)d_in[4];
    const float* b2 = (const float*)d_in[5];
    float* out = (float*)d_out;

    cudaStream_t s2;
    cudaEvent_t evFork, evJoin, evG, evA[NCHUNK];
    cudaStreamCreateWithFlags(&s2, cudaStreamNonBlocking);
    cudaEventCreateWithFlags(&evFork, cudaEventDisableTiming);
    cudaEventCreateWithFlags(&evJoin, cudaEventDisableTiming);
    cudaEventCreateWithFlags(&evG, cudaEventDisableTiming);
    for (int c = 0; c < NCHUNK; c++)
        cudaEventCreateWithFlags(&evA[c], cudaEventDisableTiming);

    cudaEventRecord(evFork, 0);
    cudaStreamWaitEvent(s2, evFork, 0);

    // --- CSR branch (stream s2): degrees, scan(+dis), fin, fill ---
    k_zero_indeg<<<(NN + 255) / 256, 256, 0, s2>>>();
    k_deg_count<<<(NE / 4 + 255) / 256, 256, 0, s2>>>(ei);
    k_scan_blk<<<SCAN_B, 1024, 0, s2>>>();
    k_scan_fin<<<SCAN_B, 1024, 0, s2>>>();
    k_csr_fill<<<(NE / 4 + 255) / 256, 256, 0, s2>>>(ei);
    cudaEventRecord(evJoin, s2);

    // --- main branch (stream 0): GEMM1 overlapped with CSR build ---
    k_gemm_mma<128, 0><<<(NN + 127) / 128, 256>>>(x, W1, 0, NN);
    cudaStreamWaitEvent(0, evJoin, 0);

    // --- chunk-pipelined agg128 (stream 0) -> gemm2 (stream s2) ---
    for (int c = 0; c < NCHUNK; c++) {
        int n0 = c * CHUNK;
        int n1 = (n0 + CHUNK < NN) ? n0 + CHUNK : NN;
        int nodes = n1 - n0;
        k_agg<128><<<(nodes * 32 + 255) / 256, 256>>>(b1, nullptr, n0, n1);
        cudaEventRecord(evA[c], 0);
        cudaStreamWaitEvent(s2, evA[c], 0);
        k_gemm_mma<64, 1><<<(nodes + 127) / 128, 256, 0, s2>>>(nullptr, W2, n0, NN);
    }
    cudaEventRecord(evG, s2);
    cudaStreamWaitEvent(0, evG, 0);

    k_agg<64><<<(NN * 32 + 255) / 256, 256>>>(b2, out, 0, NN);

    for (int c = 0; c < NCHUNK; c++) cudaEventDestroy(evA[c]);
    cudaEventDestroy(evFork);
    cudaEventDestroy(evJoin);
    cudaEventDestroy(evG);
    cudaStreamDestroy(s2);
}

// round 14
// speedup vs baseline: 1.0831x; 1.0831x over previous
#include <cuda_runtime.h>
#include <cuda_fp16.h>
#include <cstdint>

// ---------------------------------------------------------------------------
// 2-layer GCN:  out = Â( relu( Â(xW1)+b1 ) W2 ) + b2,  Â = D^-1/2 (A+I) D^-1/2
// edge_index is INT32.
// GEMMs: HMMA mma.sync.m16n8k16 (fp16 in, fp32 accum), H stored fp16.
// GEMM2 epilogue pre-scales rows by dis[row]; agg64 needs no per-edge dis.
// CSR build overlapped with GEMM1 (single fork-join). Scan = ONE kernel with
// an all-arrive grid barrier (98 blocks < 148 SMs -> co-resident, safe).
// ---------------------------------------------------------------------------

static constexpr int NN = 100000;
static constexpr int NE = 1600000;
static constexpr int SCAN_B = (NN + 1023) / 1024;   // 98 blocks

__device__ __half g_hh1[(size_t)NN * 128];  // x @ W1                  (fp16)
__device__ __half g_r1[(size_t)NN * 128];   // relu(Â h1 + b1)         (fp16)
__device__ __half g_hh2[(size_t)NN * 64];   // dis[row]*(relu(a1)@W2)  (fp16)
__device__ float  g_dis[NN];                // (1+indeg)^-1/2
__device__ int    g_indeg[NN];
__device__ int    g_bsum[SCAN_B];
__device__ int    g_rowptr[NN + 1];
__device__ int    g_cursor[NN];
__device__ int    g_csrc[NE];               // CSR src ids (grouped by dst)
__device__ int    g_barrier;                // scan grid barrier (reset each call)

// ---------------------------------------------------------------------------
// helpers
// ---------------------------------------------------------------------------
__device__ __forceinline__ unsigned h2u(__half2 h) {
    return *reinterpret_cast<unsigned*>(&h);
}
__device__ __forceinline__ float2 u2f2(unsigned u) {
    return __half22float2(*reinterpret_cast<__half2*>(&u));
}
__device__ __forceinline__ void mma16816(float* c, const unsigned* a,
                                         const unsigned* b) {
    asm volatile(
        "mma.sync.aligned.m16n8k16.row.col.f32.f16.f16.f32 "
        "{%0,%1,%2,%3}, {%4,%5,%6,%7}, {%8,%9}, {%0,%1,%2,%3};"
        : "+f"(c[0]), "+f"(c[1]), "+f"(c[2]), "+f"(c[3])
        : "r"(a[0]), "r"(a[1]), "r"(a[2]), "r"(a[3]), "r"(b[0]), "r"(b[1]));
}

// ---------------------------------------------------------------------------
// degree count (int4-vectorized; NE % 4 == 0). Also resets the scan barrier.
// ---------------------------------------------------------------------------
__global__ void k_zero_indeg() {
    int i = blockIdx.x * blockDim.x + threadIdx.x;
    if (i < NN) g_indeg[i] = 0;
    if (i == 0) g_barrier = 0;
}

__global__ void k_deg_count(const int* __restrict__ ei) {
    int i = blockIdx.x * blockDim.x + threadIdx.x;
    if (i < NE / 4) {
        int4 d = ((const int4*)(ei + NE))[i];
        atomicAdd(&g_indeg[d.x], 1);
        atomicAdd(&g_indeg[d.y], 1);
        atomicAdd(&g_indeg[d.z], 1);
        atomicAdd(&g_indeg[d.w], 1);
    }
}

// ---------------------------------------------------------------------------
// single-kernel scan: block scan + all-arrive grid barrier + offset + store.
// 98 blocks, all co-resident (< 148 SMs); concurrent gemm1 drains -> no deadlock.
// ---------------------------------------------------------------------------
__global__ void __launch_bounds__(1024) k_scan() {
    __shared__ int wsum[32];
    __shared__ int s_off, s_tot;
    const int t = threadIdx.x, lane = t & 31, wid = t >> 5;
    const int idx = blockIdx.x * 1024 + t;

    int deg = (idx < NN) ? g_indeg[idx] : 0;
    if (idx < NN) g_dis[idx] = rsqrtf((float)(deg + 1));   // fused k_dis

    // block-wide inclusive scan (2-level shuffle)
    int s = deg;
#pragma unroll
    for (int o = 1; o < 32; o <<= 1) {
        int n = __shfl_up_sync(0xffffffffu, s, o);
        if (lane >= o) s += n;
    }
    if (lane == 31) wsum[wid] = s;
    __syncthreads();
    if (wid == 0) {
        int ws = wsum[lane];
#pragma unroll
        for (int o = 1; o < 32; o <<= 1) {
            int n = __shfl_up_sync(0xffffffffu, ws, o);
            if (lane >= o) ws += n;
        }
        wsum[lane] = ws;
    }
    __syncthreads();
    const int incl = (wid ? wsum[wid - 1] : 0) + s;        // block-local inclusive

    // publish block total, arrive, wait for all
    if (t == 1023) {
        g_bsum[blockIdx.x] = incl;
        __threadfence();
        atomicAdd(&g_barrier, 1);
    }
    if (t == 0) {
        while (atomicAdd(&g_barrier, 0) < SCAN_B) __nanosleep(64);
    }
    __syncthreads();

    // block offset = sum of preceding block totals (warp 0 reduces)
    if (t < 32) {
        int pre = 0, tot = 0;
        for (int i = t; i < SCAN_B; i += 32) {
            int v = g_bsum[i];
            tot += v;
            if (i < blockIdx.x) pre += v;
        }
#pragma unroll
        for (int o = 16; o; o >>= 1) {
            pre += __shfl_down_sync(0xffffffffu, pre, o);
            tot += __shfl_down_sync(0xffffffffu, tot, o);
        }
        if (t == 0) { s_off = pre; s_tot = tot; }
    }
    __syncthreads();

    if (idx < NN) {
        int r = incl - deg + s_off;                        // exclusive
        g_rowptr[idx] = r;
        g_cursor[idx] = r;
    }
    if (blockIdx.x == SCAN_B - 1 && t == 0) g_rowptr[NN] = s_tot;
}

__global__ void k_csr_fill(const int* __restrict__ ei) {
    int i = blockIdx.x * blockDim.x + threadIdx.x;
    if (i < NE / 4) {
        int4 s = ((const int4*)ei)[i];
        int4 d = ((const int4*)(ei + NE))[i];
        g_csrc[atomicAdd(&g_cursor[d.x], 1)] = s.x;
        g_csrc[atomicAdd(&g_cursor[d.y], 1)] = s.y;
        g_csrc[atomicAdd(&g_cursor[d.z], 1)] = s.z;
        g_csrc[atomicAdd(&g_cursor[d.w], 1)] = s.w;
    }
}

// ---------------------------------------------------------------------------
// HMMA GEMM: H[M,BN] = A[M,128] @ W[128,BN], fp16 in, fp32 accum, fp16 out.
// 256 thr = 8 warps (4m x 2n), BM=128, KC=64.
// SRC=0: A = x (fp32, converted), store h.
// SRC=1: A = g_r1 (fp16), store dis[row]*h   (pre-scaled for agg64).
// ---------------------------------------------------------------------------
template <int BN, int SRC>
__global__ void __launch_bounds__(256, 2)
k_gemm_mma(const float* __restrict__ Ap, const float* __restrict__ W, int M) {
    constexpr int K   = 128;
    constexpr int KC  = 64;
    constexpr int BM  = 128;
    constexpr int SA  = KC + 8;          // 72 halfs (conflict-free fragments)
    constexpr int SB  = KC + 8;
    constexpr int WN  = BN / 2;          // warp n-tile (64 or 32)
    constexpr int NT  = WN / 8;          // n8 tiles per warp (8 or 4)

    __shared__ __half As[BM * SA];       // [m][k]
    __shared__ __half Bs[BN * SB];       // [n][k]  (transposed for col-major B)

    const int tid  = threadIdx.x;
    const int wid  = tid >> 5;
    const int lane = tid & 31;
    const int gid  = lane >> 2;          // 0..7
    const int tig  = lane & 3;           // 0..3
    const int wm   = wid >> 1;           // 0..3
    const int wn   = wid & 1;            // 0..1
    const int rowbase = blockIdx.x * BM;

    float acc[2][NT][4];
#pragma unroll
    for (int mi = 0; mi < 2; mi++)
#pragma unroll
        for (int nj = 0; nj < NT; nj++)
#pragma unroll
            for (int q = 0; q < 4; q++) acc[mi][nj][q] = 0.f;

    for (int kk = 0; kk < K; kk += KC) {
        // --- A chunk (BM x 64) -> As[m][k] fp16 ---
        if (SRC == 0) {
            const float4* A4 = (const float4*)Ap;
#pragma unroll
            for (int t = 0; t < 8; t++) {
                int f  = tid + t * 256;
                int r  = f >> 4;             // 16 float4 per 64-col row
                int c4 = f & 15;
                int grow = rowbase + r;
                float4 v = make_float4(0.f, 0.f, 0.f, 0.f);
                if (grow < M) v = A4[(size_t)grow * 32 + (kk >> 2) + c4];
                uint2 pk;
                pk.x = h2u(__floats2half2_rn(v.x, v.y));
                pk.y = h2u(__floats2half2_rn(v.z, v.w));
                *(uint2*)&As[r * SA + c4 * 4] = pk;
            }
        } else {
            const uint2* A2 = (const uint2*)g_r1;   // 4 halfs per uint2, 32/row
#pragma unroll
            for (int t = 0; t < 8; t++) {
                int f  = tid + t * 256;
                int r  = f >> 4;
                int c4 = f & 15;
                int grow = rowbase + r;
                uint2 v = make_uint2(0u, 0u);
                if (grow < M) v = A2[(size_t)grow * 32 + (kk >> 2) + c4];
                *(uint2*)&As[r * SA + c4 * 4] = v;
            }
        }
        // --- W chunk (64 x BN) -> Bs[n][k] fp16 (transpose; coalesced reads) ---
        {
            constexpr int TPN  = 256 / BN;     // threads per n (2 or 4)
            constexpr int KPER = KC / TPN;     // k's per thread (32 or 16)
            int n  = tid % BN;
            int kb = (tid / BN) * KPER;
#pragma unroll
            for (int i = 0; i < KPER; i++) {
                float v = W[(size_t)(kk + kb + i) * BN + n];
                Bs[n * SB + kb + i] = __float2half_rn(v);
            }
        }
        __syncthreads();

#pragma unroll
        for (int ks = 0; ks < KC / 16; ks++) {
            unsigned a[2][4];
#pragma unroll
            for (int mi = 0; mi < 2; mi++) {
                const __half* base =
                    &As[(wm * 32 + mi * 16 + gid) * SA + ks * 16 + tig * 2];
                a[mi][0] = *(const unsigned*)base;
                a[mi][1] = *(const unsigned*)(base + 8 * SA);
                a[mi][2] = *(const unsigned*)(base + 8);
                a[mi][3] = *(const unsigned*)(base + 8 * SA + 8);
            }
#pragma unroll
            for (int nj = 0; nj < NT; nj++) {
                const __half* bb =
                    &Bs[(wn * WN + nj * 8 + gid) * SB + ks * 16 + tig * 2];
                unsigned b[2];
                b[0] = *(const unsigned*)bb;
                b[1] = *(const unsigned*)(bb + 8);
                mma16816(acc[0][nj], a[0], b);
                mma16816(acc[1][nj], a[1], b);
            }
        }
        __syncthreads();
    }

    // --- epilogue: fp16 store of H (SRC==1: pre-scaled by dis[row]) ---
    __half* H = (SRC == 0) ? g_hh1 : g_hh2;
#pragma unroll
    for (int mi = 0; mi < 2; mi++) {
#pragma unroll
        for (int rr = 0; rr < 2; rr++) {
            int grow = rowbase + wm * 32 + mi * 16 + gid + rr * 8;
            if (grow < M) {
                float sc = (SRC == 1) ? g_dis[grow] : 1.0f;
#pragma unroll
                for (int nj = 0; nj < NT; nj++) {
                    int n = wn * WN + nj * 8 + tig * 2;
                    float v0 = acc[mi][nj][rr * 2];
                    float v1 = acc[mi][nj][rr * 2 + 1];
                    if (SRC == 1) { v0 *= sc; v1 *= sc; }
                    *(unsigned*)&H[(size_t)grow * BN + n] =
                        h2u(__floats2half2_rn(v0, v1));
                }
            }
        }
    }
}

// ---------------------------------------------------------------------------
// aggregation, warp-per-node, fp32 accumulate.
// C=128 (h=g_hh1, raw):  r1[w] = relu( dw*(dw*h[w] + Σ dis[s]*h[s]) + b )  fp16
// C=64  (h=g_hh2, pre-scaled): out[w] = dw*(hh2[w] + Σ hh2[s]) + b         fp32
// ---------------------------------------------------------------------------
template <int C>
__global__ void __launch_bounds__(256)
k_agg(const float* __restrict__ bias, float* __restrict__ outp) {
    const __half* h = (C == 128) ? g_hh1 : g_hh2;

    const int w = (blockIdx.x * blockDim.x + threadIdx.x) >> 5;
    if (w >= NN) return;
    const int lane = threadIdx.x & 31;
    const int beg = g_rowptr[w];
    const int end = g_rowptr[w + 1];
    const float dw = g_dis[w];

    if constexpr (C == 128) {
        const uint2* h8 = (const uint2*)h;          // 4 halfs per uint2, 32/row
        uint2 raw = h8[(size_t)w * 32 + lane];
        float2 f0 = u2f2(raw.x), f1 = u2f2(raw.y);
        float4 acc = make_float4(f0.x * dw, f0.y * dw, f1.x * dw, f1.y * dw);
        int j = beg;
        for (; j + 3 < end; j += 4) {               // 4-way for MLP
            int   s0 = g_csrc[j],   s1 = g_csrc[j+1], s2 = g_csrc[j+2], s3 = g_csrc[j+3];
            float w0 = g_dis[s0],   w1 = g_dis[s1],   w2 = g_dis[s2],   w3 = g_dis[s3];
            uint2 r0 = __ldg(h8 + (size_t)s0 * 32 + lane);
            uint2 r1 = __ldg(h8 + (size_t)s1 * 32 + lane);
            uint2 r2 = __ldg(h8 + (size_t)s2 * 32 + lane);
            uint2 r3 = __ldg(h8 + (size_t)s3 * 32 + lane);
            float2 a0 = u2f2(r0.x), b0 = u2f2(r0.y);
            float2 a1 = u2f2(r1.x), b1 = u2f2(r1.y);
            float2 a2 = u2f2(r2.x), b2 = u2f2(r2.y);
            float2 a3 = u2f2(r3.x), b3 = u2f2(r3.y);
            acc.x = fmaf(a0.x, w0, acc.x); acc.y = fmaf(a0.y, w0, acc.y);
            acc.z = fmaf(b0.x, w0, acc.z); acc.w = fmaf(b0.y, w0, acc.w);
            acc.x = fmaf(a1.x, w1, acc.x); acc.y = fmaf(a1.y, w1, acc.y);
            acc.z = fmaf(b1.x, w1, acc.z); acc.w = fmaf(b1.y, w1, acc.w);
            acc.x = fmaf(a2.x, w2, acc.x); acc.y = fmaf(a2.y, w2, acc.y);
            acc.z = fmaf(b2.x, w2, acc.z); acc.w = fmaf(b2.y, w2, acc.w);
            acc.x = fmaf(a3.x, w3, acc.x); acc.y = fmaf(a3.y, w3, acc.y);
            acc.z = fmaf(b3.x, w3, acc.z); acc.w = fmaf(b3.y, w3, acc.w);
        }
        for (; j < end; j++) {
            int   s0 = g_csrc[j];
            float w0 = g_dis[s0];
            uint2 r0 = __ldg(h8 + (size_t)s0 * 32 + lane);
            float2 a0 = u2f2(r0.x), b0 = u2f2(r0.y);
            acc.x = fmaf(a0.x, w0, acc.x); acc.y = fmaf(a0.y, w0, acc.y);
            acc.z = fmaf(b0.x, w0, acc.z); acc.w = fmaf(b0.y, w0, acc.w);
        }
        const float4 bb = ((const float4*)bias)[lane];
        float rx = fmaxf(fmaf(acc.x, dw, bb.x), 0.f);
        float ry = fmaxf(fmaf(acc.y, dw, bb.y), 0.f);
        float rz = fmaxf(fmaf(acc.z, dw, bb.z), 0.f);
        float rw = fmaxf(fmaf(acc.w, dw, bb.w), 0.f);
        uint2 pk;
        pk.x = h2u(__floats2half2_rn(rx, ry));
        pk.y = h2u(__floats2half2_rn(rz, rw));
        ((uint2*)g_r1)[(size_t)w * 32 + lane] = pk;   // relu(a1) in fp16
    } else {
        const unsigned* h4 = (const unsigned*)h;    // 2 halfs per u32, 32/row
        float2 hv = u2f2(h4[(size_t)w * 32 + lane]);
        float2 acc = hv;                            // hh2[w] = dw*h2[w] already
        int j = beg;
        for (; j + 3 < end; j += 4) {
            int s0 = g_csrc[j], s1 = g_csrc[j+1], s2 = g_csrc[j+2], s3 = g_csrc[j+3];
            float2 v0 = u2f2(__ldg(h4 + (size_t)s0 * 32 + lane));
            float2 v1 = u2f2(__ldg(h4 + (size_t)s1 * 32 + lane));
            float2 v2 = u2f2(__ldg(h4 + (size_t)s2 * 32 + lane));
            float2 v3 = u2f2(__ldg(h4 + (size_t)s3 * 32 + lane));
            acc.x += v0.x + v1.x; acc.y += v0.y + v1.y;
            acc.x += v2.x + v3.x; acc.y += v2.y + v3.y;
        }
        for (; j < end; j++) {
            int s0 = g_csrc[j];
            float2 v0 = u2f2(__ldg(h4 + (size_t)s0 * 32 + lane));
            acc.x += v0.x; acc.y += v0.y;
        }
        const float2 bb = ((const float2*)bias)[lane];
        ((float2*)outp)[(size_t)w * 32 + lane] =
            make_float2(fmaf(acc.x, dw, bb.x), fmaf(acc.y, dw, bb.y));
    }
}

// ---------------------------------------------------------------------------
extern "C" void kernel_launch(void* const* d_in, const int* in_sizes, int n_in,
                              void* d_out, int out_size) {
    (void)in_sizes; (void)n_in; (void)out_size;
    const float* x  = (const float*)d_in[0];
    const int*   ei = (const int*)d_in[1];     // int32 (JAX x64 disabled)
    const float* W1 = (const float*)d_in[2];
    const float* b1 = (const float*)d_in[3];
    const float* W2 = (const float*)d_in[4];
    const float* b2 = (const float*)d_in[5];
    float* out = (float*)d_out;

    // fork-join: CSR build on side stream, overlapped with GEMM1
    cudaStream_t s2;
    cudaEvent_t evFork, evJoin;
    cudaStreamCreateWithFlags(&s2, cudaStreamNonBlocking);
    cudaEventCreateWithFlags(&evFork, cudaEventDisableTiming);
    cudaEventCreateWithFlags(&evJoin, cudaEventDisableTiming);

    cudaEventRecord(evFork, 0);
    cudaStreamWaitEvent(s2, evFork, 0);

    // --- CSR branch (stream s2): degrees, fused scan(+dis), fill ---
    k_zero_indeg<<<(NN + 255) / 256, 256, 0, s2>>>();
    k_deg_count<<<(NE / 4 + 255) / 256, 256, 0, s2>>>(ei);
    k_scan<<<SCAN_B, 1024, 0, s2>>>();
    k_csr_fill<<<(NE / 4 + 255) / 256, 256, 0, s2>>>(ei);
    cudaEventRecord(evJoin, s2);

    // --- main branch (stream 0): GEMM1 overlapped with CSR build ---
    k_gemm_mma<128, 0><<<(NN + 127) / 128, 256>>>(x, W1, NN);
    cudaStreamWaitEvent(0, evJoin, 0);

    k_agg<128><<<(NN * 32 + 255) / 256, 256>>>(b1, nullptr);
    k_gemm_mma<64, 1><<<(NN + 127) / 128, 256>>>(nullptr, W2, NN);
    k_agg<64><<<(NN * 32 + 255) / 256, 256>>>(b2, out);

    cudaEventDestroy(evFork);
    cudaEventDestroy(evJoin);
    cudaStreamDestroy(s2);
}

// round 15
// speedup vs baseline: 1.0896x; 1.0060x over previous
#include <cuda_runtime.h>
#include <cuda_fp16.h>
#include <cstdint>

// ---------------------------------------------------------------------------
// 2-layer GCN:  out = Â( relu( Â(xW1)+b1 ) W2 ) + b2,  Â = D^-1/2 (A+I) D^-1/2
// edge_index is INT32.
// GEMMs: HMMA mma.sync.m16n8k16 (fp16 in, fp32 accum), H stored fp16.
// GEMM2 epilogue pre-scales rows by dis[row]; agg64 needs no per-edge dis.
// CSR build overlapped with GEMM1. Count pass captures per-dst position
// (ppos) so the fill pass is ATOMIC-FREE: csrc[rowptr[d]+ppos[e]] = src[e].
// ---------------------------------------------------------------------------

static constexpr int NN = 100000;
static constexpr int NE = 1600000;
static constexpr int SCAN_B = (NN + 1023) / 1024;   // 98 blocks

__device__ __half g_hh1[(size_t)NN * 128];  // x @ W1                  (fp16)
__device__ __half g_r1[(size_t)NN * 128];   // relu(Â h1 + b1)         (fp16)
__device__ __half g_hh2[(size_t)NN * 64];   // dis[row]*(relu(a1)@W2)  (fp16)
__device__ float  g_dis[NN];                // (1+indeg)^-1/2
__device__ int    g_indeg[NN];
__device__ int    g_ppos[NE];               // per-edge rank within its dst
__device__ int    g_bsum[SCAN_B];
__device__ int    g_rowptr[NN + 1];
__device__ int    g_csrc[NE];               // CSR src ids (grouped by dst)
__device__ int    g_barrier;                // scan grid barrier (reset each call)

// ---------------------------------------------------------------------------
// helpers
// ---------------------------------------------------------------------------
__device__ __forceinline__ unsigned h2u(__half2 h) {
    return *reinterpret_cast<unsigned*>(&h);
}
__device__ __forceinline__ float2 u2f2(unsigned u) {
    return __half22float2(*reinterpret_cast<__half2*>(&u));
}
__device__ __forceinline__ void mma16816(float* c, const unsigned* a,
                                         const unsigned* b) {
    asm volatile(
        "mma.sync.aligned.m16n8k16.row.col.f32.f16.f16.f32 "
        "{%0,%1,%2,%3}, {%4,%5,%6,%7}, {%8,%9}, {%0,%1,%2,%3};"
        : "+f"(c[0]), "+f"(c[1]), "+f"(c[2]), "+f"(c[3])
        : "r"(a[0]), "r"(a[1]), "r"(a[2]), "r"(a[3]), "r"(b[0]), "r"(b[1]));
}

// ---------------------------------------------------------------------------
// CSR build
// ---------------------------------------------------------------------------
__global__ void k_zero_indeg() {
    int i = blockIdx.x * blockDim.x + threadIdx.x;
    if (i < NN) g_indeg[i] = 0;
    if (i == 0) g_barrier = 0;
}

// count + position capture (int4-vectorized; NE % 4 == 0)
__global__ void k_count_pos(const int* __restrict__ ei) {
    int i = blockIdx.x * blockDim.x + threadIdx.x;
    if (i < NE / 4) {
        int4 d = ((const int4*)(ei + NE))[i];
        int4 p;
        p.x = atomicAdd(&g_indeg[d.x], 1);
        p.y = atomicAdd(&g_indeg[d.y], 1);
        p.z = atomicAdd(&g_indeg[d.z], 1);
        p.w = atomicAdd(&g_indeg[d.w], 1);
        ((int4*)g_ppos)[i] = p;
    }
}

// single-kernel scan: block scan + all-arrive grid barrier + offset + store.
// 98 blocks, all co-resident (< 148 SMs); concurrent gemm1 drains -> no deadlock.
__global__ void __launch_bounds__(1024) k_scan() {
    __shared__ int wsum[32];
    __shared__ int s_off, s_tot;
    const int t = threadIdx.x, lane = t & 31, wid = t >> 5;
    const int idx = blockIdx.x * 1024 + t;

    int deg = (idx < NN) ? g_indeg[idx] : 0;
    if (idx < NN) g_dis[idx] = rsqrtf((float)(deg + 1));   // fused k_dis

    int s = deg;
#pragma unroll
    for (int o = 1; o < 32; o <<= 1) {
        int n = __shfl_up_sync(0xffffffffu, s, o);
        if (lane >= o) s += n;
    }
    if (lane == 31) wsum[wid] = s;
    __syncthreads();
    if (wid == 0) {
        int ws = wsum[lane];
#pragma unroll
        for (int o = 1; o < 32; o <<= 1) {
            int n = __shfl_up_sync(0xffffffffu, ws, o);
            if (lane >= o) ws += n;
        }
        wsum[lane] = ws;
    }
    __syncthreads();
    const int incl = (wid ? wsum[wid - 1] : 0) + s;        // block-local inclusive

    if (t == 1023) {
        g_bsum[blockIdx.x] = incl;
        __threadfence();
        atomicAdd(&g_barrier, 1);
    }
    if (t == 0) {
        while (atomicAdd(&g_barrier, 0) < SCAN_B) __nanosleep(64);
    }
    __syncthreads();

    if (t < 32) {
        int pre = 0, tot = 0;
        for (int i = t; i < SCAN_B; i += 32) {
            int v = g_bsum[i];
            tot += v;
            if (i < blockIdx.x) pre += v;
        }
#pragma unroll
        for (int o = 16; o; o >>= 1) {
            pre += __shfl_down_sync(0xffffffffu, pre, o);
            tot += __shfl_down_sync(0xffffffffu, tot, o);
        }
        if (t == 0) { s_off = pre; s_tot = tot; }
    }
    __syncthreads();

    if (idx < NN) g_rowptr[idx] = incl - deg + s_off;      // exclusive
    if (blockIdx.x == SCAN_B - 1 && t == 0) g_rowptr[NN] = s_tot;
}

// atomic-free fill: csrc[rowptr[d] + ppos[e]] = src[e]
__global__ void k_fill(const int* __restrict__ ei) {
    int i = blockIdx.x * blockDim.x + threadIdx.x;
    if (i < NE / 4) {
        int4 s = ((const int4*)ei)[i];
        int4 d = ((const int4*)(ei + NE))[i];
        int4 p = ((const int4*)g_ppos)[i];
        int r0 = __ldg(&g_rowptr[d.x]);
        int r1 = __ldg(&g_rowptr[d.y]);
        int r2 = __ldg(&g_rowptr[d.z]);
        int r3 = __ldg(&g_rowptr[d.w]);
        g_csrc[r0 + p.x] = s.x;
        g_csrc[r1 + p.y] = s.y;
        g_csrc[r2 + p.z] = s.z;
        g_csrc[r3 + p.w] = s.w;
    }
}

// ---------------------------------------------------------------------------
// HMMA GEMM: H[M,BN] = A[M,128] @ W[128,BN], fp16 in, fp32 accum, fp16 out.
// 256 thr = 8 warps (4m x 2n), BM=128, KC=64.
// SRC=0: A = x (fp32, converted), store h.
// SRC=1: A = g_r1 (fp16), store dis[row]*h   (pre-scaled for agg64).
// ---------------------------------------------------------------------------
template <int BN, int SRC>
__global__ void __launch_bounds__(256, 2)
k_gemm_mma(const float* __restrict__ Ap, const float* __restrict__ W, int M) {
    constexpr int K   = 128;
    constexpr int KC  = 64;
    constexpr int BM  = 128;
    constexpr int SA  = KC + 8;          // 72 halfs (conflict-free fragments)
    constexpr int SB  = KC + 8;
    constexpr int WN  = BN / 2;          // warp n-tile (64 or 32)
    constexpr int NT  = WN / 8;          // n8 tiles per warp (8 or 4)

    __shared__ __half As[BM * SA];       // [m][k]
    __shared__ __half Bs[BN * SB];       // [n][k]  (transposed for col-major B)

    const int tid  = threadIdx.x;
    const int wid  = tid >> 5;
    const int lane = tid & 31;
    const int gid  = lane >> 2;          // 0..7
    const int tig  = lane & 3;           // 0..3
    const int wm   = wid >> 1;           // 0..3
    const int wn   = wid & 1;            // 0..1
    const int rowbase = blockIdx.x * BM;

    float acc[2][NT][4];
#pragma unroll
    for (int mi = 0; mi < 2; mi++)
#pragma unroll
        for (int nj = 0; nj < NT; nj++)
#pragma unroll
            for (int q = 0; q < 4; q++) acc[mi][nj][q] = 0.f;

    for (int kk = 0; kk < K; kk += KC) {
        // --- A chunk (BM x 64) -> As[m][k] fp16 ---
        if (SRC == 0) {
            const float4* A4 = (const float4*)Ap;
#pragma unroll
            for (int t = 0; t < 8; t++) {
                int f  = tid + t * 256;
                int r  = f >> 4;             // 16 float4 per 64-col row
                int c4 = f & 15;
                int grow = rowbase + r;
                float4 v = make_float4(0.f, 0.f, 0.f, 0.f);
                if (grow < M) v = A4[(size_t)grow * 32 + (kk >> 2) + c4];
                uint2 pk;
                pk.x = h2u(__floats2half2_rn(v.x, v.y));
                pk.y = h2u(__floats2half2_rn(v.z, v.w));
                *(uint2*)&As[r * SA + c4 * 4] = pk;
            }
        } else {
            const uint2* A2 = (const uint2*)g_r1;   // 4 halfs per uint2, 32/row
#pragma unroll
            for (int t = 0; t < 8; t++) {
                int f  = tid + t * 256;
                int r  = f >> 4;
                int c4 = f & 15;
                int grow = rowbase + r;
                uint2 v = make_uint2(0u, 0u);
                if (grow < M) v = A2[(size_t)grow * 32 + (kk >> 2) + c4];
                *(uint2*)&As[r * SA + c4 * 4] = v;
            }
        }
        // --- W chunk (64 x BN) -> Bs[n][k] fp16 (transpose; coalesced reads) ---
        {
            constexpr int TPN  = 256 / BN;     // threads per n (2 or 4)
            constexpr int KPER = KC / TPN;     // k's per thread (32 or 16)
            int n  = tid % BN;
            int kb = (tid / BN) * KPER;
#pragma unroll
            for (int i = 0; i < KPER; i++) {
                float v = W[(size_t)(kk + kb + i) * BN + n];
                Bs[n * SB + kb + i] = __float2half_rn(v);
            }
        }
        __syncthreads();

#pragma unroll
        for (int ks = 0; ks < KC / 16; ks++) {
            unsigned a[2][4];
#pragma unroll
            for (int mi = 0; mi < 2; mi++) {
                const __half* base =
                    &As[(wm * 32 + mi * 16 + gid) * SA + ks * 16 + tig * 2];
                a[mi][0] = *(const unsigned*)base;
                a[mi][1] = *(const unsigned*)(base + 8 * SA);
                a[mi][2] = *(const unsigned*)(base + 8);
                a[mi][3] = *(const unsigned*)(base + 8 * SA + 8);
            }
#pragma unroll
            for (int nj = 0; nj < NT; nj++) {
                const __half* bb =
                    &Bs[(wn * WN + nj * 8 + gid) * SB + ks * 16 + tig * 2];
                unsigned b[2];
                b[0] = *(const unsigned*)bb;
                b[1] = *(const unsigned*)(bb + 8);
                mma16816(acc[0][nj], a[0], b);
                mma16816(acc[1][nj], a[1], b);
            }
        }
        __syncthreads();
    }

    // --- epilogue: fp16 store of H (SRC==1: pre-scaled by dis[row]) ---
    __half* H = (SRC == 0) ? g_hh1 : g_hh2;
#pragma unroll
    for (int mi = 0; mi < 2; mi++) {
#pragma unroll
        for (int rr = 0; rr < 2; rr++) {
            int grow = rowbase + wm * 32 + mi * 16 + gid + rr * 8;
            if (grow < M) {
                float sc = (SRC == 1) ? g_dis[grow] : 1.0f;
#pragma unroll
                for (int nj = 0; nj < NT; nj++) {
                    int n = wn * WN + nj * 8 + tig * 2;
                    float v0 = acc[mi][nj][rr * 2];
                    float v1 = acc[mi][nj][rr * 2 + 1];
                    if (SRC == 1) { v0 *= sc; v1 *= sc; }
                    *(unsigned*)&H[(size_t)grow * BN + n] =
                        h2u(__floats2half2_rn(v0, v1));
                }
            }
        }
    }
}

// ---------------------------------------------------------------------------
// aggregation, warp-per-node, fp32 accumulate.
// C=128 (h=g_hh1, raw):  r1[w] = relu( dw*(dw*h[w] + Σ dis[s]*h[s]) + b )  fp16
// C=64  (h=g_hh2, pre-scaled): out[w] = dw*(hh2[w] + Σ hh2[s]) + b         fp32
// ---------------------------------------------------------------------------
template <int C>
__global__ void __launch_bounds__(256)
k_agg(const float* __restrict__ bias, float* __restrict__ outp) {
    const __half* h = (C == 128) ? g_hh1 : g_hh2;

    const int w = (blockIdx.x * blockDim.x + threadIdx.x) >> 5;
    if (w >= NN) return;
    const int lane = threadIdx.x & 31;
    const int beg = g_rowptr[w];
    const int end = g_rowptr[w + 1];
    const float dw = g_dis[w];

    if constexpr (C == 128) {
        const uint2* h8 = (const uint2*)h;          // 4 halfs per uint2, 32/row
        uint2 raw = h8[(size_t)w * 32 + lane];
        float2 f0 = u2f2(raw.x), f1 = u2f2(raw.y);
        float4 acc = make_float4(f0.x * dw, f0.y * dw, f1.x * dw, f1.y * dw);
        int j = beg;
        for (; j + 3 < end; j += 4) {               // 4-way for MLP
            int   s0 = g_csrc[j],   s1 = g_csrc[j+1], s2 = g_csrc[j+2], s3 = g_csrc[j+3];
            float w0 = g_dis[s0],   w1 = g_dis[s1],   w2 = g_dis[s2],   w3 = g_dis[s3];
            uint2 r0 = __ldg(h8 + (size_t)s0 * 32 + lane);
            uint2 r1 = __ldg(h8 + (size_t)s1 * 32 + lane);
            uint2 r2 = __ldg(h8 + (size_t)s2 * 32 + lane);
            uint2 r3 = __ldg(h8 + (size_t)s3 * 32 + lane);
            float2 a0 = u2f2(r0.x), b0 = u2f2(r0.y);
            float2 a1 = u2f2(r1.x), b1 = u2f2(r1.y);
            float2 a2 = u2f2(r2.x), b2 = u2f2(r2.y);
            float2 a3 = u2f2(r3.x), b3 = u2f2(r3.y);
            acc.x = fmaf(a0.x, w0, acc.x); acc.y = fmaf(a0.y, w0, acc.y);
            acc.z = fmaf(b0.x, w0, acc.z); acc.w = fmaf(b0.y, w0, acc.w);
            acc.x = fmaf(a1.x, w1, acc.x); acc.y = fmaf(a1.y, w1, acc.y);
            acc.z = fmaf(b1.x, w1, acc.z); acc.w = fmaf(b1.y, w1, acc.w);
            acc.x = fmaf(a2.x, w2, acc.x); acc.y = fmaf(a2.y, w2, acc.y);
            acc.z = fmaf(b2.x, w2, acc.z); acc.w = fmaf(b2.y, w2, acc.w);
            acc.x = fmaf(a3.x, w3, acc.x); acc.y = fmaf(a3.y, w3, acc.y);
            acc.z = fmaf(b3.x, w3, acc.z); acc.w = fmaf(b3.y, w3, acc.w);
        }
        for (; j < end; j++) {
            int   s0 = g_csrc[j];
            float w0 = g_dis[s0];
            uint2 r0 = __ldg(h8 + (size_t)s0 * 32 + lane);
            float2 a0 = u2f2(r0.x), b0 = u2f2(r0.y);
            acc.x = fmaf(a0.x, w0, acc.x); acc.y = fmaf(a0.y, w0, acc.y);
            acc.z = fmaf(b0.x, w0, acc.z); acc.w = fmaf(b0.y, w0, acc.w);
        }
        const float4 bb = ((const float4*)bias)[lane];
        float rx = fmaxf(fmaf(acc.x, dw, bb.x), 0.f);
        float ry = fmaxf(fmaf(acc.y, dw, bb.y), 0.f);
        float rz = fmaxf(fmaf(acc.z, dw, bb.z), 0.f);
        float rw = fmaxf(fmaf(acc.w, dw, bb.w), 0.f);
        uint2 pk;
        pk.x = h2u(__floats2half2_rn(rx, ry));
        pk.y = h2u(__floats2half2_rn(rz, rw));
        ((uint2*)g_r1)[(size_t)w * 32 + lane] = pk;   // relu(a1) in fp16
    } else {
        const unsigned* h4 = (const unsigned*)h;    // 2 halfs per u32, 32/row
        float2 hv = u2f2(h4[(size_t)w * 32 + lane]);
        float2 acc = hv;                            // hh2[w] = dw*h2[w] already
        int j = beg;
        for (; j + 3 < end; j += 4) {
            int s0 = g_csrc[j], s1 = g_csrc[j+1], s2 = g_csrc[j+2], s3 = g_csrc[j+3];
            float2 v0 = u2f2(__ldg(h4 + (size_t)s0 * 32 + lane));
            float2 v1 = u2f2(__ldg(h4 + (size_t)s1 * 32 + lane));
            float2 v2 = u2f2(__ldg(h4 + (size_t)s2 * 32 + lane));
            float2 v3 = u2f2(__ldg(h4 + (size_t)s3 * 32 + lane));
            acc.x += v0.x + v1.x; acc.y += v0.y + v1.y;
            acc.x += v2.x + v3.x; acc.y += v2.y + v3.y;
        }
        for (; j < end; j++) {
            int s0 = g_csrc[j];
            float2 v0 = u2f2(__ldg(h4 + (size_t)s0 * 32 + lane));
            acc.x += v0.x; acc.y += v0.y;
        }
        const float2 bb = ((const float2*)bias)[lane];
        ((float2*)outp)[(size_t)w * 32 + lane] =
            make_float2(fmaf(acc.x, dw, bb.x), fmaf(acc.y, dw, bb.y));
    }
}

// ---------------------------------------------------------------------------
extern "C" void kernel_launch(void* const* d_in, const int* in_sizes, int n_in,
                              void* d_out, int out_size) {
    (void)in_sizes; (void)n_in; (void)out_size;
    const float* x  = (const float*)d_in[0];
    const int*   ei = (const int*)d_in[1];     // int32 (JAX x64 disabled)
    const float* W1 = (const float*)d_in[2];
    const float* b1 = (const float*)d_in[3];
    const float* W2 = (const float*)d_in[4];
    const float* b2 = (const float*)d_in[5];
    float* out = (float*)d_out;

    // fork-join: CSR build on side stream, overlapped with GEMM1
    cudaStream_t s2;
    cudaEvent_t evFork, evJoin;
    cudaStreamCreateWithFlags(&s2, cudaStreamNonBlocking);
    cudaEventCreateWithFlags(&evFork, cudaEventDisableTiming);
    cudaEventCreateWithFlags(&evJoin, cudaEventDisableTiming);

    cudaEventRecord(evFork, 0);
    cudaStreamWaitEvent(s2, evFork, 0);

    // --- CSR branch (stream s2): count+pos, fused scan(+dis), atomic-free fill ---
    k_zero_indeg<<<(NN + 255) / 256, 256, 0, s2>>>();
    k_count_pos<<<(NE / 4 + 255) / 256, 256, 0, s2>>>(ei);
    k_scan<<<SCAN_B, 1024, 0, s2>>>();
    k_fill<<<(NE / 4 + 255) / 256, 256, 0, s2>>>(ei);
    cudaEventRecord(evJoin, s2);

    // --- main branch (stream 0): GEMM1 overlapped with CSR build ---
    k_gemm_mma<128, 0><<<(NN + 127) / 128, 256>>>(x, W1, NN);
    cudaStreamWaitEvent(0, evJoin, 0);

    k_agg<128><<<(NN * 32 + 255) / 256, 256>>>(b1, nullptr);
    k_gemm_mma<64, 1><<<(NN + 127) / 128, 256>>>(nullptr, W2, NN);
    k_agg<64><<<(NN * 32 + 255) / 256, 256>>>(b2, out);

    cudaEventDestroy(evFork);
    cudaEventDestroy(evJoin);
    cudaStreamDestroy(s2);
}